// round 2
// baseline (speedup 1.0000x reference)
#include <cuda_runtime.h>
#include <cuda_bf16.h>
#include <cstdint>

typedef unsigned long long ull;

// ---------------- problem constants ----------------
#define BATCH 64
#define DIN   176
#define HID   512
#define G4    2048          // 4*HID
#define T_ENC 1025          // 1 + 1024
#define T_DEC 1023          // TTGT - 1
#define MROWS_MAX (BATCH * T_ENC)   // 65600

// ---------------- scratch (static device globals; no cudaMalloc allowed) ----
__device__ float g_gx  [(size_t)MROWS_MAX * G4];   // per-layer gx, also reused as hmid
__device__ float g_seqA[(size_t)MROWS_MAX * HID];  // hidden sequence buffer
__device__ float g_seqB[(size_t)MROWS_MAX * HID];  // dec_out
__device__ float g_xpad[(size_t)MROWS_MAX * DIN];  // padded inputs
__device__ float g_hpub[2 * BATCH * HID];          // ping-pong published h
__device__ float g_hT0[BATCH * HID], g_cT0[BATCH * HID];
__device__ float g_hT1[BATCH * HID], g_cT1[BATCH * HID];
__device__ float g_hTd[BATCH * HID], g_cTd[BATCH * HID];
__device__ unsigned g_bar[4];

// ---------------- f32x2 packed-FMA helpers (sm_103a FFMA2) ----------------
__device__ __forceinline__ ull dup2(float x) {
    ull r; asm("mov.b64 %0, {%1, %1};" : "=l"(r) : "f"(x)); return r;
}
__device__ __forceinline__ void fma2(ull& a, ull w, ull h) {
    asm("fma.rn.f32x2 %0, %1, %2, %0;" : "+l"(a) : "l"(w), "l"(h));
}

// ---------------- small utility kernels ----------------
__global__ void reset_bar_kernel(unsigned* bar) {
    if (threadIdx.x < 4) bar[threadIdx.x] = 0u;
}

// dst[b][t][:] = (t==0 || t>Tcopy) ? 0 : src[b][t-1][:]
__global__ void pad_shift_kernel(const float* __restrict__ src, float* __restrict__ dst,
                                 int Tsrc, int Tpad, int Tcopy) {
    long n = (long)BATCH * Tpad * DIN;
    long i = (long)blockIdx.x * blockDim.x + threadIdx.x;
    if (i >= n) return;
    int d = (int)(i % DIN);
    long bt = i / DIN;
    int t = (int)(bt % Tpad);
    int b = (int)(bt / Tpad);
    dst[i] = (t == 0 || t > Tcopy) ? 0.f : src[((long)b * Tsrc + (t - 1)) * DIN + d];
}

__global__ void zero_t0_kernel(float* __restrict__ out) {
    int i = blockIdx.x * blockDim.x + threadIdx.x;
    if (i < BATCH * DIN) {
        int b = i / DIN, d = i % DIN;
        out[(size_t)b * 1024 * DIN + d] = 0.f;
    }
}

// ---------------- fp32 GEMM: C = A(MxK) * W(NxK)^T + b1 + b2 ----------------
// 128x128 CTA tile, 256 threads, 8x8 per-thread micro tile via FFMA2,
// double-buffered smem. K%8==0 required.
// remapT>0: row m -> (b=m/remapT, t=m%remapT) stored at row b*(remapT+1)+t+1 (ld=N).
__global__ void __launch_bounds__(256, 2)
gemm_bias_kernel(const float* __restrict__ A, const float* __restrict__ W,
                 const float* __restrict__ b1, const float* __restrict__ b2,
                 float* __restrict__ C, int M, int N, int K,
                 int relu, int remapT) {
    __shared__ __align__(16) float As[2][8][132];
    __shared__ __align__(16) float Bs[2][8][132];
    const int row0 = blockIdx.y * 128;
    const int col0 = blockIdx.x * 128;
    const int tid = threadIdx.x;
    const int lm = tid >> 1;
    const int lk = (tid & 1) * 4;
    const int tx = tid & 15;
    const int ty = tid >> 4;

    ull acc2[8][4];
#pragma unroll
    for (int i = 0; i < 8; i++)
#pragma unroll
        for (int j = 0; j < 4; j++) acc2[i][j] = 0ull;

    const int nk = K >> 3;
    const bool aok = (row0 + lm) < M;
    const bool bok = (col0 + lm) < N;
    const float* aptr = A + (size_t)(row0 + lm) * K + lk;
    const float* bptr = W + (size_t)(col0 + lm) * K + lk;

    float4 av = aok ? *(const float4*)aptr : make_float4(0.f, 0.f, 0.f, 0.f);
    float4 bv = bok ? *(const float4*)bptr : make_float4(0.f, 0.f, 0.f, 0.f);
    As[0][lk + 0][lm] = av.x; As[0][lk + 1][lm] = av.y;
    As[0][lk + 2][lm] = av.z; As[0][lk + 3][lm] = av.w;
    Bs[0][lk + 0][lm] = bv.x; Bs[0][lk + 1][lm] = bv.y;
    Bs[0][lk + 2][lm] = bv.z; Bs[0][lk + 3][lm] = bv.w;
    __syncthreads();

    for (int ic = 0; ic < nk; ic++) {
        const int cur = ic & 1;
        if (ic + 1 < nk) {
            av = aok ? *(const float4*)(aptr + (ic + 1) * 8) : make_float4(0.f, 0.f, 0.f, 0.f);
            bv = bok ? *(const float4*)(bptr + (ic + 1) * 8) : make_float4(0.f, 0.f, 0.f, 0.f);
        }
#pragma unroll
        for (int k = 0; k < 8; k++) {
            float a8[8];
            *(float4*)&a8[0] = *(const float4*)&As[cur][k][ty * 8];
            *(float4*)&a8[4] = *(const float4*)&As[cur][k][ty * 8 + 4];
            ull bp[4];
            *(ulonglong2*)&bp[0] = *(const ulonglong2*)&Bs[cur][k][tx * 8];
            *(ulonglong2*)&bp[2] = *(const ulonglong2*)&Bs[cur][k][tx * 8 + 4];
#pragma unroll
            for (int i = 0; i < 8; i++) {
                ull ad = dup2(a8[i]);
#pragma unroll
                for (int p = 0; p < 4; p++) fma2(acc2[i][p], bp[p], ad);
            }
        }
        if (ic + 1 < nk) {
            const int nx = cur ^ 1;
            As[nx][lk + 0][lm] = av.x; As[nx][lk + 1][lm] = av.y;
            As[nx][lk + 2][lm] = av.z; As[nx][lk + 3][lm] = av.w;
            Bs[nx][lk + 0][lm] = bv.x; Bs[nx][lk + 1][lm] = bv.y;
            Bs[nx][lk + 2][lm] = bv.z; Bs[nx][lk + 3][lm] = bv.w;
        }
        __syncthreads();
    }

#pragma unroll
    for (int i = 0; i < 8; i++) {
        int r = row0 + ty * 8 + i;
        if (r >= M) continue;
        size_t rowbase;
        if (remapT > 0) {
            int bb = r / remapT;
            int tt = r - bb * remapT;
            rowbase = ((size_t)bb * (remapT + 1) + tt + 1) * (size_t)N;
        } else {
            rowbase = (size_t)r * N;
        }
#pragma unroll
        for (int p = 0; p < 4; p++) {
            float2 v = *(float2*)&acc2[i][p];
            int c0 = col0 + tx * 8 + 2 * p;
            if (c0 < N) {
                float o = v.x + (b1 ? b1[c0] : 0.f) + (b2 ? b2[c0] : 0.f);
                if (relu) o = fmaxf(o, 0.f);
                C[rowbase + c0] = o;
            }
            if (c0 + 1 < N) {
                float o = v.y + (b1 ? b1[c0 + 1] : 0.f) + (b2 ? b2[c0 + 1] : 0.f);
                if (relu) o = fmaxf(o, 0.f);
                C[rowbase + c0 + 1] = o;
            }
        }
    }
}

// ---------------- persistent LSTM scan ----------------
// Grid: 128 CTAs = 4 batch-groups(16 batches) x 32 hidden-tiles(16 hidden).
// Whh slice (64 gate-rows x 512) lives in smem for the whole scan.
// c state in registers. h published through ping-pong global buffer + sw barrier.
#define SCAN_SMEM_FLOATS (512 * 68 + 512 * 20 + 8192)
#define SCAN_SMEM_BYTES  (SCAN_SMEM_FLOATS * 4)

__device__ __forceinline__ float sigf(float x) { return 1.f / (1.f + expf(-x)); }

__device__ __forceinline__ void group_barrier(unsigned* bar, int bg, unsigned target) {
    __threadfence();          // release: make this CTA's global writes visible
    __syncthreads();
    if (threadIdx.x == 0) {
        atomicAdd(&bar[bg], 1u);
        while (atomicAdd(&bar[bg], 0u) < target) { }
        __threadfence();      // acquire side
    }
    __syncthreads();
}

__global__ void __launch_bounds__(256, 1)
lstm_scan_kernel(const float* __restrict__ gx, const float* __restrict__ Whh,
                 const float* __restrict__ h0, const float* __restrict__ c0,
                 float* __restrict__ hs_out, float* __restrict__ hT_out,
                 float* __restrict__ cT_out, float* __restrict__ hpub,
                 unsigned* __restrict__ bar, int T) {
    extern __shared__ float sm[];
    float* w_s = sm;                    // [512][68]  transposed weights w_s[k*68+gr]
    float* h_s = w_s + 512 * 68;        // [512][20]  transposed h_prev  h_s[k*20+b]
    float* red = h_s + 512 * 20;        // [8][16][64] partials red[s*1024+b*64+gr]

    const int tid = threadIdx.x;
    const int bg = blockIdx.x >> 5;     // batch group 0..3
    const int ht = blockIdx.x & 31;     // hidden tile 0..31
    const int B0 = bg * 16;
    const int J0 = ht * 16;

    // ---- load Whh slice into smem (once) ----
    {
        int gr = tid >> 2;              // 0..63  (g = gr>>4, j = gr&15)
        int g = gr >> 4, j = gr & 15;
        int k0 = (tid & 3) * 128;
        const float* wrow = Whh + ((size_t)(g * 512 + J0 + j)) * 512 + k0;
#pragma unroll 4
        for (int k = 0; k < 128; k++) w_s[(k0 + k) * 68 + gr] = wrow[k];
    }

    // ---- init states ----
    const int ub = tid >> 4;            // batch within tile (0..15)
    const int uj = tid & 15;            // hidden within tile (0..15)
    float cval = c0 ? c0[(B0 + ub) * 512 + J0 + uj] : 0.f;
    float hval = h0 ? h0[(B0 + ub) * 512 + J0 + uj] : 0.f;
    hpub[32768 + (B0 + ub) * 512 + J0 + uj] = hval;   // parity-1 slot feeds t=0

    unsigned nbar = 1;
    group_barrier(bar, bg, nbar * 32);

    // compute-phase thread mapping
    const int s   = tid >> 5;           // k-slice 0..7 (64 k each)
    const int o   = tid & 31;
    const int ob2 = (o >> 3) << 2;      // batch sub-offset 0,4,8,12
    const int og8 = (o & 7) << 3;       // gate-row sub-offset 0..56

    const float* gxrow = gx + ((size_t)(B0 + ub) * T) * G4 + J0 + uj;
    float* hsrow = hs_out ? hs_out + ((size_t)(B0 + ub) * T) * 512 + J0 + uj : nullptr;

    for (int t = 0; t < T; ++t) {
        // prefetch gx for this step (independent of barrier-published data)
        float pgi = gxrow[0], pgf = gxrow[512], pgg = gxrow[1024], pgo = gxrow[1536];

        const float* hsrc = hpub + (((t + 1) & 1) << 15);   // *32768

        // phase 1: load h_prev (L2-coherent, vectorized)
#pragma unroll
        for (int i = 0; i < 8; ++i) {
            int idx = tid + (i << 8);       // 0..2047
            int b = idx >> 7;               // 0..15
            int k4 = (idx & 127) << 2;      // 0..508
            float4 hv = __ldcg((const float4*)(hsrc + (B0 + b) * 512 + k4));
            h_s[(k4 + 0) * 20 + b] = hv.x;
            h_s[(k4 + 1) * 20 + b] = hv.y;
            h_s[(k4 + 2) * 20 + b] = hv.z;
            h_s[(k4 + 3) * 20 + b] = hv.w;
        }
        __syncthreads();

        // phase 2: partial dot products, 4 batches x 8 gate-rows over 64 k (FFMA2)
        ull acc[4][4];
#pragma unroll
        for (int bb = 0; bb < 4; bb++)
#pragma unroll
            for (int p = 0; p < 4; p++) acc[bb][p] = 0ull;

        const float* hptr = &h_s[(s * 64) * 20 + ob2];
        const float* wptr = &w_s[(s * 64) * 68 + og8];
#pragma unroll 8
        for (int kk = 0; kk < 64; ++kk) {
            float4 h4 = *(const float4*)hptr;  hptr += 20;
            ull wp[4];
            *(ulonglong2*)&wp[0] = *(const ulonglong2*)wptr;
            *(ulonglong2*)&wp[2] = *(const ulonglong2*)(wptr + 4);
            wptr += 68;
            ull hx = dup2(h4.x), hy = dup2(h4.y), hz = dup2(h4.z), hw = dup2(h4.w);
#pragma unroll
            for (int p = 0; p < 4; p++) {
                fma2(acc[0][p], wp[p], hx);
                fma2(acc[1][p], wp[p], hy);
                fma2(acc[2][p], wp[p], hz);
                fma2(acc[3][p], wp[p], hw);
            }
        }

        // phase 3: write partials
#pragma unroll
        for (int bb = 0; bb < 4; bb++) {
            int base = s * 1024 + (ob2 + bb) * 64 + og8;
            *(ulonglong2*)&red[base]     = *(ulonglong2*)&acc[bb][0];
            *(ulonglong2*)&red[base + 4] = *(ulonglong2*)&acc[bb][2];
        }
        __syncthreads();

        // phase 4: reduce k-slices, add gx, elementwise LSTM cell (thread = (b,j))
        float gi = 0.f, gf = 0.f, gg = 0.f, go = 0.f;
#pragma unroll
        for (int s2 = 0; s2 < 8; s2++) {
            const float* rp = &red[s2 * 1024 + ub * 64 + uj];
            gi += rp[0]; gf += rp[16]; gg += rp[32]; go += rp[48];
        }
        gi += pgi; gf += pgf; gg += pgg; go += pgo;

        float ig = sigf(gi), fg = sigf(gf), og_ = sigf(go), gt = tanhf(gg);
        cval = fg * cval + ig * gt;
        hval = og_ * tanhf(cval);

        hpub[((t & 1) << 15) + (B0 + ub) * 512 + J0 + uj] = hval;
        if (hsrow) { *hsrow = hval; hsrow += 512; }
        gxrow += G4;

        ++nbar;
        group_barrier(bar, bg, nbar * 32);
    }

    hT_out[(B0 + ub) * 512 + J0 + uj] = hval;
    cT_out[(B0 + ub) * 512 + J0 + uj] = cval;
}

// ---------------- host orchestration ----------------
static void launch_gemm(const float* A, const float* W, const float* b1, const float* b2,
                        float* C, int M, int N, int K, int relu, int remapT) {
    dim3 grid((N + 127) / 128, (M + 127) / 128);
    gemm_bias_kernel<<<grid, 256>>>(A, W, b1, b2, C, M, N, K, relu, remapT);
}

extern "C" void kernel_launch(void* const* d_in, const int* in_sizes, int n_in,
                              void* d_out, int out_size) {
    (void)in_sizes; (void)n_in; (void)out_size;
    const float* x        = (const float*)d_in[0];
    const float* y        = (const float*)d_in[1];
    const float* eWih0    = (const float*)d_in[2];
    const float* eWhh0    = (const float*)d_in[3];
    const float* ebih0    = (const float*)d_in[4];
    const float* ebhh0    = (const float*)d_in[5];
    const float* eWih1    = (const float*)d_in[6];
    const float* eWhh1    = (const float*)d_in[7];
    const float* ebih1    = (const float*)d_in[8];
    const float* ebhh1    = (const float*)d_in[9];
    const float* dWih0    = (const float*)d_in[10];
    const float* dWhh0    = (const float*)d_in[11];
    const float* dbih0    = (const float*)d_in[12];
    const float* dbhh0    = (const float*)d_in[13];
    const float* dWih1    = (const float*)d_in[14];
    const float* dWhh1    = (const float*)d_in[15];
    const float* dbih1    = (const float*)d_in[16];
    const float* dbhh1    = (const float*)d_in[17];
    const float* clsW1    = (const float*)d_in[18];
    const float* clsb1    = (const float*)d_in[19];
    const float* clsW2    = (const float*)d_in[20];
    const float* clsb2    = (const float*)d_in[21];
    float* out = (float*)d_out;

    float *gx, *seqA, *seqB, *xpad, *hpub, *hT0, *cT0, *hT1, *cT1, *hTd, *cTd;
    unsigned* bar;
    cudaGetSymbolAddress((void**)&gx,   g_gx);
    cudaGetSymbolAddress((void**)&seqA, g_seqA);
    cudaGetSymbolAddress((void**)&seqB, g_seqB);
    cudaGetSymbolAddress((void**)&xpad, g_xpad);
    cudaGetSymbolAddress((void**)&hpub, g_hpub);
    cudaGetSymbolAddress((void**)&hT0,  g_hT0);
    cudaGetSymbolAddress((void**)&cT0,  g_cT0);
    cudaGetSymbolAddress((void**)&hT1,  g_hT1);
    cudaGetSymbolAddress((void**)&cT1,  g_cT1);
    cudaGetSymbolAddress((void**)&hTd,  g_hTd);
    cudaGetSymbolAddress((void**)&cTd,  g_cTd);
    cudaGetSymbolAddress((void**)&bar,  g_bar);

    cudaFuncSetAttribute(lstm_scan_kernel,
                         cudaFuncAttributeMaxDynamicSharedMemorySize, SCAN_SMEM_BYTES);

    const int ME = BATCH * T_ENC;   // 65600
    const int MD = BATCH * T_DEC;   // 65472

    // ---------------- encoder ----------------
    {
        long n = (long)BATCH * T_ENC * DIN;
        pad_shift_kernel<<<(int)((n + 255) / 256), 256>>>(x, xpad, 1024, T_ENC, 1024);
    }
    launch_gemm(xpad, eWih0, ebih0, ebhh0, gx, ME, G4, DIN, 0, 0);
    reset_bar_kernel<<<1, 32>>>(bar);
    lstm_scan_kernel<<<128, 256, SCAN_SMEM_BYTES>>>(gx, eWhh0, nullptr, nullptr,
                                                    seqA, hT0, cT0, hpub, bar, T_ENC);
    launch_gemm(seqA, eWih1, ebih1, ebhh1, gx, ME, G4, HID, 0, 0);
    reset_bar_kernel<<<1, 32>>>(bar);
    lstm_scan_kernel<<<128, 256, SCAN_SMEM_BYTES>>>(gx, eWhh1, nullptr, nullptr,
                                                    nullptr, hT1, cT1, hpub, bar, T_ENC);

    // ---------------- decoder ----------------
    {
        long n = (long)BATCH * T_DEC * DIN;
        pad_shift_kernel<<<(int)((n + 255) / 256), 256>>>(y, xpad, 1024, T_DEC, 1022);
    }
    launch_gemm(xpad, dWih0, dbih0, dbhh0, gx, MD, G4, DIN, 0, 0);
    reset_bar_kernel<<<1, 32>>>(bar);
    lstm_scan_kernel<<<128, 256, SCAN_SMEM_BYTES>>>(gx, dWhh0, hT0, cT0,
                                                    seqA, hTd, cTd, hpub, bar, T_DEC);
    launch_gemm(seqA, dWih1, dbih1, dbhh1, gx, MD, G4, HID, 0, 0);
    reset_bar_kernel<<<1, 32>>>(bar);
    lstm_scan_kernel<<<128, 256, SCAN_SMEM_BYTES>>>(gx, dWhh1, hT1, cT1,
                                                    seqB, hTd, cTd, hpub, bar, T_DEC);

    // ---------------- classifier ----------------
    // hmid = relu(dec_out @ W1^T + b1)  -> stored in gx buffer (ld = 256)
    launch_gemm(seqB, clsW1, clsb1, nullptr, gx, MD, 256, HID, 1, 0);
    // logits -> out[b][t+1][:], row remap, ld = DIN
    launch_gemm(gx, clsW2, clsb2, nullptr, out, MD, DIN, 256, 0, T_DEC);
    zero_t0_kernel<<<(BATCH * DIN + 255) / 256, 256>>>(out);
}

// round 3
// speedup vs baseline: 1.1333x; 1.1333x over previous
#include <cuda_runtime.h>
#include <cuda_bf16.h>
#include <cstdint>

typedef unsigned long long ull;

// ---------------- problem constants ----------------
#define BATCH 64
#define DIN   176
#define HID   512
#define G4    2048          // 4*HID
#define T_ENC 1025          // 1 + 1024
#define T_DEC 1023          // TTGT - 1
#define MROWS_MAX (BATCH * T_ENC)   // 65600

// ---------------- scratch (static device globals; no cudaMalloc allowed) ----
__device__ float g_gx  [(size_t)MROWS_MAX * G4];   // per-layer gx, also reused as hmid
__device__ float g_seqA[(size_t)MROWS_MAX * HID];  // hidden sequence buffer
__device__ float g_seqB[(size_t)MROWS_MAX * HID];  // dec_out
__device__ float g_xpad[(size_t)MROWS_MAX * DIN];  // padded inputs
__device__ float g_hpub[2 * BATCH * HID];          // ping-pong published h
__device__ float g_hT0[BATCH * HID], g_cT0[BATCH * HID];
__device__ float g_hT1[BATCH * HID], g_cT1[BATCH * HID];
__device__ float g_hTd[BATCH * HID], g_cTd[BATCH * HID];
__device__ unsigned g_bar[4];

// ---------------- f32x2 packed-FMA helpers (sm_103a FFMA2) ----------------
__device__ __forceinline__ ull pack2(float x, float y) {
    ull r; asm("mov.b64 %0, {%1, %2};" : "=l"(r) : "f"(x), "f"(y)); return r;
}
__device__ __forceinline__ void fma2(ull& a, ull w, ull h) {
    asm("fma.rn.f32x2 %0, %1, %2, %0;" : "+l"(a) : "l"(w), "l"(h));
}

// ---------------- small utility kernels ----------------
__global__ void reset_bar_kernel(unsigned* bar) {
    if (threadIdx.x < 4) bar[threadIdx.x] = 0u;
}

// dst[b][t][:] = (t==0 || t>Tcopy) ? 0 : src[b][t-1][:]
__global__ void pad_shift_kernel(const float* __restrict__ src, float* __restrict__ dst,
                                 int Tsrc, int Tpad, int Tcopy) {
    long n = (long)BATCH * Tpad * DIN;
    long i = (long)blockIdx.x * blockDim.x + threadIdx.x;
    if (i >= n) return;
    int d = (int)(i % DIN);
    long bt = i / DIN;
    int t = (int)(bt % Tpad);
    int b = (int)(bt / Tpad);
    dst[i] = (t == 0 || t > Tcopy) ? 0.f : src[((long)b * Tsrc + (t - 1)) * DIN + d];
}

__global__ void zero_t0_kernel(float* __restrict__ out) {
    int i = blockIdx.x * blockDim.x + threadIdx.x;
    if (i < BATCH * DIN) {
        int b = i / DIN, d = i % DIN;
        out[(size_t)b * 1024 * DIN + d] = 0.f;
    }
}

// ---------------- generic fp32 GEMM (round-1 proven version) ---------------
// C = A(MxK) * W(NxK)^T + b1 + b2. 128x128 CTA tile, 256 threads, 8x8 micro.
__global__ void __launch_bounds__(256, 2)
gemm_bias_kernel(const float* __restrict__ A, const float* __restrict__ W,
                 const float* __restrict__ b1, const float* __restrict__ b2,
                 float* __restrict__ C, int M, int N, int K,
                 int relu, int remapT) {
    __shared__ float As[8][132];
    __shared__ float Bs[8][132];
    const int row0 = blockIdx.y * 128;
    const int col0 = blockIdx.x * 128;
    const int tid = threadIdx.x;
    const int lm = tid >> 1;
    const int lk = (tid & 1) * 4;
    const int tx = tid & 15;
    const int ty = tid >> 4;

    float acc[8][8];
#pragma unroll
    for (int i = 0; i < 8; i++)
#pragma unroll
        for (int j = 0; j < 8; j++) acc[i][j] = 0.f;

    for (int kc = 0; kc < K; kc += 8) {
        float4 av = make_float4(0.f, 0.f, 0.f, 0.f);
        int ar = row0 + lm;
        if (ar < M) av = *(const float4*)&A[(size_t)ar * K + kc + lk];
        As[lk + 0][lm] = av.x; As[lk + 1][lm] = av.y;
        As[lk + 2][lm] = av.z; As[lk + 3][lm] = av.w;

        float4 bv = make_float4(0.f, 0.f, 0.f, 0.f);
        int wr = col0 + lm;
        if (wr < N) bv = *(const float4*)&W[(size_t)wr * K + kc + lk];
        Bs[lk + 0][lm] = bv.x; Bs[lk + 1][lm] = bv.y;
        Bs[lk + 2][lm] = bv.z; Bs[lk + 3][lm] = bv.w;
        __syncthreads();

#pragma unroll
        for (int k = 0; k < 8; k++) {
            float a[8], b[8];
            *(float4*)&a[0] = *(float4*)&As[k][ty * 8];
            *(float4*)&a[4] = *(float4*)&As[k][ty * 8 + 4];
            *(float4*)&b[0] = *(float4*)&Bs[k][tx * 8];
            *(float4*)&b[4] = *(float4*)&Bs[k][tx * 8 + 4];
#pragma unroll
            for (int i = 0; i < 8; i++)
#pragma unroll
                for (int j = 0; j < 8; j++) acc[i][j] += a[i] * b[j];
        }
        __syncthreads();
    }

#pragma unroll
    for (int j = 0; j < 8; j++) {
        int cidx = col0 + tx * 8 + j;
        if (cidx >= N) continue;
        float bias = (b1 ? b1[cidx] : 0.f) + (b2 ? b2[cidx] : 0.f);
#pragma unroll
        for (int i = 0; i < 8; i++) {
            int r = row0 + ty * 8 + i;
            if (r >= M) continue;
            size_t rowbase;
            if (remapT > 0) {
                int bb = r / remapT;
                int tt = r - bb * remapT;
                rowbase = ((size_t)bb * (remapT + 1) + tt + 1) * (size_t)N;
            } else {
                rowbase = (size_t)r * N;
            }
            float v = acc[i][j] + bias;
            if (relu) v = fmaxf(v, 0.f);
            C[rowbase + cidx] = v;
        }
    }
}

// ---------------- persistent LSTM scan (register-resident weights) ---------
// Grid: 128 CTAs = 4 batch-groups(16 batches) x 32 hidden-tiles(16 hidden).
// Each CTA: 64 gate-rows x 512 k x 16 batches per step.
// Thread (w=warp 0..7, l=lane 0..31): owns gate-row pair (2l,2l+1) and
// k-slice [w*64, w*64+64), weights packed f32x2 in 64 ull registers.
// h staged in smem PRE-DUPLICATED as (h,h) ull pairs -> phase 2 has no MOVs.
#define SCAN_H_ULL   (512 * 16)            // h_d: [k][b] dup pairs, 64 KB
#define SCAN_RED_ULL (8 * 32 * 17)         // red: [s][l][b] pad 17, ~34.8 KB
#define SCAN_SMEM_BYTES ((SCAN_H_ULL + SCAN_RED_ULL) * 8)

__device__ __forceinline__ float sigf(float x) { return 1.f / (1.f + expf(-x)); }

__device__ __forceinline__ void group_barrier(unsigned* bar, int bg, unsigned target) {
    __threadfence();          // release: make this CTA's global writes visible
    __syncthreads();
    if (threadIdx.x == 0) {
        atomicAdd(&bar[bg], 1u);
        while (atomicAdd(&bar[bg], 0u) < target) { }
        __threadfence();      // acquire side
    }
    __syncthreads();
}

__global__ void __launch_bounds__(256, 1)
lstm_scan_kernel(const float* __restrict__ gx, const float* __restrict__ Whh,
                 const float* __restrict__ h0, const float* __restrict__ c0,
                 float* __restrict__ hs_out, float* __restrict__ hT_out,
                 float* __restrict__ cT_out, float* __restrict__ hpub,
                 unsigned* __restrict__ bar, int T) {
    extern __shared__ __align__(16) ull smu[];
    ull* h_d = smu;                     // [512][16] : (h,h) pair at [k*16+b]
    ull* red = smu + SCAN_H_ULL;        // [8][32][17]

    const int tid = threadIdx.x;
    const int bg = blockIdx.x >> 5;     // batch group 0..3
    const int ht = blockIdx.x & 31;     // hidden tile 0..31
    const int B0 = bg * 16;
    const int J0 = ht * 16;
    const int w = tid >> 5;             // warp: k-slice
    const int l = tid & 31;             // lane: gate-row pair (2l, 2l+1)

    // ---- load Whh row-pair slice into registers (once) ----
    ull wreg[64];
    {
        const int r0 = 2 * l;                      // rows within 64: same gate g
        const int g = r0 >> 4, j = r0 & 15;        // j even, j+1 = second row
        const float* p0 = Whh + ((size_t)(g * 512 + J0 + j)) * 512 + w * 64;
        const float* p1 = p0 + 512;
#pragma unroll
        for (int kk = 0; kk < 64; kk++)
            wreg[kk] = pack2(__ldg(p0 + kk), __ldg(p1 + kk));
    }

    // ---- init states ----
    const int ub = tid >> 4;            // batch within tile (0..15)
    const int uj = tid & 15;            // hidden within tile (0..15)
    float cval = c0 ? c0[(B0 + ub) * 512 + J0 + uj] : 0.f;
    float hval = h0 ? h0[(B0 + ub) * 512 + J0 + uj] : 0.f;
    hpub[32768 + (B0 + ub) * 512 + J0 + uj] = hval;   // parity-1 slot feeds t=0

    unsigned nbar = 1;
    group_barrier(bar, bg, nbar * 32);

    // phase-1 mapping: lane covers batch (tid&15), kq base (tid>>4)
    const int p1b = tid & 15;
    const int p1k = tid >> 4;           // 0..15

    const float* gxrow = gx + ((size_t)(B0 + ub) * T) * G4 + J0 + uj;
    float* hsrow = hs_out ? hs_out + ((size_t)(B0 + ub) * T) * 512 + J0 + uj : nullptr;

    for (int t = 0; t < T; ++t) {
        // gx prefetch (input-only, hides DRAM latency under phase 2)
        float pgi = gxrow[0], pgf = gxrow[512], pgg = gxrow[1024], pgo = gxrow[1536];

        const float* hsrc = hpub + (((t + 1) & 1) << 15);

        // phase 1: load h (L2-coherent) and store DUPLICATED pairs to smem
#pragma unroll
        for (int i = 0; i < 8; ++i) {
            int kq = p1k + (i << 4);    // 0..127 (float4 index within row)
            float4 hv = __ldcg((const float4*)(hsrc + (B0 + p1b) * 512 + (kq << 2)));
            h_d[((kq << 2) + 0) * 16 + p1b] = pack2(hv.x, hv.x);
            h_d[((kq << 2) + 1) * 16 + p1b] = pack2(hv.y, hv.y);
            h_d[((kq << 2) + 2) * 16 + p1b] = pack2(hv.z, hv.z);
            h_d[((kq << 2) + 3) * 16 + p1b] = pack2(hv.w, hv.w);
        }
        __syncthreads();

        // phase 2: pure FFMA2 stream, weights in regs, h dup-pairs from smem
        ull pacc[16];
#pragma unroll
        for (int b = 0; b < 16; b++) pacc[b] = 0ull;

        const ull* hk = h_d + (w << 6) * 16;    // k base = w*64
#pragma unroll
        for (int kk = 0; kk < 64; ++kk) {
#pragma unroll
            for (int b2 = 0; b2 < 16; b2 += 2) {
                ulonglong2 h2 = *(const ulonglong2*)(hk + kk * 16 + b2);
                fma2(pacc[b2],     wreg[kk], h2.x);
                fma2(pacc[b2 + 1], wreg[kk], h2.y);
            }
        }

        // phase 3: write row-pair partials (pad-17 layout, ~2-way conflicts)
        {
            ull* rp = red + (w * 32 + l) * 17;
#pragma unroll
            for (int b = 0; b < 16; b++) rp[b] = pacc[b];
        }
        __syncthreads();

        // phase 4: reduce 8 k-slices, add gx, LSTM cell (thread = (ub,uj))
        const float* fred = (const float*)red;
        float gsum[4];
#pragma unroll
        for (int g = 0; g < 4; g++) {
            const int ll = g * 8 + (uj >> 1);   // row-pair index of row g*16+uj
            const int comp = uj & 1;
            float v = 0.f;
#pragma unroll
            for (int s2 = 0; s2 < 8; s2++)
                v += fred[2 * (((s2 << 5) + ll) * 17 + ub) + comp];
            gsum[g] = v;
        }
        float gi = gsum[0] + pgi, gf = gsum[1] + pgf;
        float gg = gsum[2] + pgg, go = gsum[3] + pgo;

        float ig = sigf(gi), fg = sigf(gf), og_ = sigf(go), gt = tanhf(gg);
        cval = fg * cval + ig * gt;
        hval = og_ * tanhf(cval);

        hpub[((t & 1) << 15) + (B0 + ub) * 512 + J0 + uj] = hval;
        if (hsrow) { *hsrow = hval; hsrow += 512; }
        gxrow += G4;

        ++nbar;
        group_barrier(bar, bg, nbar * 32);
    }

    hT_out[(B0 + ub) * 512 + J0 + uj] = hval;
    cT_out[(B0 + ub) * 512 + J0 + uj] = cval;
}

// ---------------- host orchestration ----------------
static void launch_gemm(const float* A, const float* W, const float* b1, const float* b2,
                        float* C, int M, int N, int K, int relu, int remapT) {
    dim3 grid((N + 127) / 128, (M + 127) / 128);
    gemm_bias_kernel<<<grid, 256>>>(A, W, b1, b2, C, M, N, K, relu, remapT);
}

extern "C" void kernel_launch(void* const* d_in, const int* in_sizes, int n_in,
                              void* d_out, int out_size) {
    (void)in_sizes; (void)n_in; (void)out_size;
    const float* x        = (const float*)d_in[0];
    const float* y        = (const float*)d_in[1];
    const float* eWih0    = (const float*)d_in[2];
    const float* eWhh0    = (const float*)d_in[3];
    const float* ebih0    = (const float*)d_in[4];
    const float* ebhh0    = (const float*)d_in[5];
    const float* eWih1    = (const float*)d_in[6];
    const float* eWhh1    = (const float*)d_in[7];
    const float* ebih1    = (const float*)d_in[8];
    const float* ebhh1    = (const float*)d_in[9];
    const float* dWih0    = (const float*)d_in[10];
    const float* dWhh0    = (const float*)d_in[11];
    const float* dbih0    = (const float*)d_in[12];
    const float* dbhh0    = (const float*)d_in[13];
    const float* dWih1    = (const float*)d_in[14];
    const float* dWhh1    = (const float*)d_in[15];
    const float* dbih1    = (const float*)d_in[16];
    const float* dbhh1    = (const float*)d_in[17];
    const float* clsW1    = (const float*)d_in[18];
    const float* clsb1    = (const float*)d_in[19];
    const float* clsW2    = (const float*)d_in[20];
    const float* clsb2    = (const float*)d_in[21];
    float* out = (float*)d_out;

    float *gx, *seqA, *seqB, *xpad, *hpub, *hT0, *cT0, *hT1, *cT1, *hTd, *cTd;
    unsigned* bar;
    cudaGetSymbolAddress((void**)&gx,   g_gx);
    cudaGetSymbolAddress((void**)&seqA, g_seqA);
    cudaGetSymbolAddress((void**)&seqB, g_seqB);
    cudaGetSymbolAddress((void**)&xpad, g_xpad);
    cudaGetSymbolAddress((void**)&hpub, g_hpub);
    cudaGetSymbolAddress((void**)&hT0,  g_hT0);
    cudaGetSymbolAddress((void**)&cT0,  g_cT0);
    cudaGetSymbolAddress((void**)&hT1,  g_hT1);
    cudaGetSymbolAddress((void**)&cT1,  g_cT1);
    cudaGetSymbolAddress((void**)&hTd,  g_hTd);
    cudaGetSymbolAddress((void**)&cTd,  g_cTd);
    cudaGetSymbolAddress((void**)&bar,  g_bar);

    cudaFuncSetAttribute(lstm_scan_kernel,
                         cudaFuncAttributeMaxDynamicSharedMemorySize, SCAN_SMEM_BYTES);

    const int ME = BATCH * T_ENC;   // 65600
    const int MD = BATCH * T_DEC;   // 65472

    // ---------------- encoder ----------------
    {
        long n = (long)BATCH * T_ENC * DIN;
        pad_shift_kernel<<<(int)((n + 255) / 256), 256>>>(x, xpad, 1024, T_ENC, 1024);
    }
    launch_gemm(xpad, eWih0, ebih0, ebhh0, gx, ME, G4, DIN, 0, 0);
    reset_bar_kernel<<<1, 32>>>(bar);
    lstm_scan_kernel<<<128, 256, SCAN_SMEM_BYTES>>>(gx, eWhh0, nullptr, nullptr,
                                                    seqA, hT0, cT0, hpub, bar, T_ENC);
    launch_gemm(seqA, eWih1, ebih1, ebhh1, gx, ME, G4, HID, 0, 0);
    reset_bar_kernel<<<1, 32>>>(bar);
    lstm_scan_kernel<<<128, 256, SCAN_SMEM_BYTES>>>(gx, eWhh1, nullptr, nullptr,
                                                    nullptr, hT1, cT1, hpub, bar, T_ENC);

    // ---------------- decoder ----------------
    {
        long n = (long)BATCH * T_DEC * DIN;
        pad_shift_kernel<<<(int)((n + 255) / 256), 256>>>(y, xpad, 1024, T_DEC, 1022);
    }
    launch_gemm(xpad, dWih0, dbih0, dbhh0, gx, MD, G4, DIN, 0, 0);
    reset_bar_kernel<<<1, 32>>>(bar);
    lstm_scan_kernel<<<128, 256, SCAN_SMEM_BYTES>>>(gx, dWhh0, hT0, cT0,
                                                    seqA, hTd, cTd, hpub, bar, T_DEC);
    launch_gemm(seqA, dWih1, dbih1, dbhh1, gx, MD, G4, HID, 0, 0);
    reset_bar_kernel<<<1, 32>>>(bar);
    lstm_scan_kernel<<<128, 256, SCAN_SMEM_BYTES>>>(gx, dWhh1, hT1, cT1,
                                                    seqB, hTd, cTd, hpub, bar, T_DEC);

    // ---------------- classifier ----------------
    launch_gemm(seqB, clsW1, clsb1, nullptr, gx, MD, 256, HID, 1, 0);
    launch_gemm(gx, clsW2, clsb2, nullptr, out, MD, DIN, 256, 0, T_DEC);
    zero_t0_kernel<<<(BATCH * DIN + 255) / 256, 256>>>(out);
}